// round 1
// baseline (speedup 1.0000x reference)
#include <cuda_runtime.h>
#include <cuda_bf16.h>

// Wasserstein CT cost-matrix mean.
// Algebraic identity: mean(matrix) = 2(C-1)/C^2 * mean(|ct|).
// The pairwise |organ_l - seg_c| term per pixel sums (over all c,l) to
// 2(C-1)*|ct[p]| regardless of target/pred values, so only ct matters.

#define RED_BLOCKS 256
#define RED_THREADS 256

__device__ float g_partials[RED_BLOCKS];

__device__ __forceinline__ float warp_reduce_sum(float v) {
    #pragma unroll
    for (int off = 16; off > 0; off >>= 1)
        v += __shfl_xor_sync(0xFFFFFFFFu, v, off);
    return v;
}

__global__ void __launch_bounds__(RED_THREADS)
abs_sum_stage1(const float* __restrict__ ct, int n) {
    __shared__ float s_warp[RED_THREADS / 32];

    const int tid = threadIdx.x;
    const int gtid = blockIdx.x * RED_THREADS + tid;
    const int gstride = gridDim.x * RED_THREADS;

    float acc = 0.0f;

    // Vectorized main body over float4 chunks (grid-stride for robustness).
    const int nv4 = n >> 2;
    const float4* __restrict__ ct4 = reinterpret_cast<const float4*>(ct);
    for (int i = gtid; i < nv4; i += gstride) {
        float4 v = ct4[i];
        acc += fabsf(v.x) + fabsf(v.y) + fabsf(v.z) + fabsf(v.w);
    }
    // Tail (n not multiple of 4): handled by global thread 0.
    if (gtid == 0) {
        for (int i = nv4 << 2; i < n; i++) acc += fabsf(ct[i]);
    }

    // Block reduction.
    acc = warp_reduce_sum(acc);
    if ((tid & 31) == 0) s_warp[tid >> 5] = acc;
    __syncthreads();
    if (tid < 32) {
        float v = (tid < RED_THREADS / 32) ? s_warp[tid] : 0.0f;
        v = warp_reduce_sum(v);
        if (tid == 0) g_partials[blockIdx.x] = v;
    }
}

__global__ void __launch_bounds__(RED_BLOCKS)
abs_sum_stage2(float* __restrict__ out, float scale) {
    __shared__ float s_warp[RED_BLOCKS / 32];
    const int tid = threadIdx.x;

    float v = g_partials[tid];
    v = warp_reduce_sum(v);
    if ((tid & 31) == 0) s_warp[tid >> 5] = v;
    __syncthreads();
    if (tid < 32) {
        float w = (tid < RED_BLOCKS / 32) ? s_warp[tid] : 0.0f;
        w = warp_reduce_sum(w);
        if (tid == 0) out[0] = w * scale;
    }
}

extern "C" void kernel_launch(void* const* d_in, const int* in_sizes, int n_in,
                              void* d_out, int out_size) {
    // Inputs (metadata order): pred_stage1 [1,C,H,W] f32, ct [1,H,W] f32,
    // target [1,1,H,W] i64. Only ct is needed (see identity above).
    const float* ct = (const float*)d_in[1];
    const int n = in_sizes[1];                 // H*W
    const int C = (n > 0) ? (in_sizes[0] / n) : 1;  // class count from pred size

    // mean(matrix) = 2(C-1)/(C^2 * N) * sum(|ct|)
    const double scale_d = (2.0 * (double)(C - 1)) /
                           ((double)C * (double)C * (double)n);
    const float scale = (float)scale_d;

    float* out = (float*)d_out;

    abs_sum_stage1<<<RED_BLOCKS, RED_THREADS>>>(ct, n);
    abs_sum_stage2<<<1, RED_BLOCKS>>>(out, scale);
}

// round 2
// speedup vs baseline: 1.1971x; 1.1971x over previous
#include <cuda_runtime.h>
#include <cuda_bf16.h>

// Wasserstein CT cost-matrix mean.
// Algebraic identity: mean(matrix) = 2(C-1)/C^2 * mean(|ct|).
// Per pixel, sum_{c,l} |1{t==l} - 1{q==c}| = 2(C-1) regardless of t,q.
// So only ct matters: result = 2(C-1)/(C^2*N) * sum(|ct|).
//
// Single fused kernel: block partials + last-block final reduction.
// Deterministic: partials land in fixed slots; final reduce is a fixed-order
// tree in one block; ticket counter is reset by the last block so every
// graph replay starts from the same state.

#define RED_BLOCKS 128
#define RED_THREADS 256

__device__ float g_partials[RED_BLOCKS];
__device__ unsigned int g_ticket;  // zero-initialized; reset each call by last block

__device__ __forceinline__ float warp_reduce_sum(float v) {
    #pragma unroll
    for (int off = 16; off > 0; off >>= 1)
        v += __shfl_xor_sync(0xFFFFFFFFu, v, off);
    return v;
}

__global__ void __launch_bounds__(RED_THREADS)
abs_mean_fused(const float* __restrict__ ct, int n, float scale,
               float* __restrict__ out) {
    __shared__ float s_warp[RED_THREADS / 32];
    __shared__ bool s_is_last;

    const int tid = threadIdx.x;
    const int gtid = blockIdx.x * RED_THREADS + tid;
    const int gstride = gridDim.x * RED_THREADS;

    float acc = 0.0f;

    // Vectorized grid-stride over float4 chunks.
    const int nv4 = n >> 2;
    const float4* __restrict__ ct4 = reinterpret_cast<const float4*>(ct);
    for (int i = gtid; i < nv4; i += gstride) {
        float4 v = ct4[i];
        acc += fabsf(v.x) + fabsf(v.y) + fabsf(v.z) + fabsf(v.w);
    }
    // Scalar tail (n not multiple of 4): global thread 0 only.
    if (gtid == 0) {
        for (int i = nv4 << 2; i < n; i++) acc += fabsf(ct[i]);
    }

    // Block reduction.
    acc = warp_reduce_sum(acc);
    if ((tid & 31) == 0) s_warp[tid >> 5] = acc;
    __syncthreads();
    if (tid < 32) {
        float v = (tid < RED_THREADS / 32) ? s_warp[tid] : 0.0f;
        v = warp_reduce_sum(v);
        if (tid == 0) {
            g_partials[blockIdx.x] = v;
            __threadfence();
            unsigned int t = atomicAdd(&g_ticket, 1u);
            s_is_last = (t == (unsigned int)(gridDim.x - 1));
        }
    }
    __syncthreads();

    // Last-arriving block does the final reduction over all partials.
    if (s_is_last) {
        float v = (tid < RED_BLOCKS) ? g_partials[tid] : 0.0f;
        v = warp_reduce_sum(v);
        if ((tid & 31) == 0) s_warp[tid >> 5] = v;
        __syncthreads();
        if (tid < 32) {
            float w = (tid < RED_THREADS / 32) ? s_warp[tid] : 0.0f;
            w = warp_reduce_sum(w);
            if (tid == 0) {
                out[0] = w * scale;
                g_ticket = 0u;  // restore state for next graph replay
            }
        }
    }
}

extern "C" void kernel_launch(void* const* d_in, const int* in_sizes, int n_in,
                              void* d_out, int out_size) {
    // Inputs (metadata order): pred_stage1 [1,C,H,W] f32, ct [1,H,W] f32,
    // target [1,1,H,W] i64. Only ct is needed (see identity above).
    const float* ct = (const float*)d_in[1];
    const int n = in_sizes[1];                      // H*W
    const int C = (n > 0) ? (in_sizes[0] / n) : 1;  // class count from pred size

    const double scale_d = (2.0 * (double)(C - 1)) /
                           ((double)C * (double)C * (double)n);
    const float scale = (float)scale_d;

    abs_mean_fused<<<RED_BLOCKS, RED_THREADS>>>(ct, n, scale, (float*)d_out);
}